// round 8
// baseline (speedup 1.0000x reference)
#include <cuda_runtime.h>
#include <cstdint>
#include <math.h>

// ---------------- problem constants ----------------
#define BB   4
#define NX   4096
#define NY   8192
#define DD   256
#define TMR  128                 // x rows per CTA
#define TNC  128                 // y cols per tile
#define KCH  32                  // k per chunk
#define NTIL (NY / TNC)          // 64 y tiles
#define NCHK (DD / KCH)          // 8 chunks per tile
#define CHTOT (NTIL * NCHK)      // 512 chunk iterations
#define KK   10
#define NVAL (BB * NX * KK)      // 163840
#define INV_TAU 20.0f
#define NTHR 512

// tf32-split scratch (row-major K-major, no transpose needed)
__device__ float g_xhi[(size_t)BB * NX * DD];
__device__ float g_xlo[(size_t)BB * NX * DD];
__device__ float g_yhi[(size_t)BB * NY * DD];
__device__ float g_ylo[(size_t)BB * NY * DD];

// ---------------- smem layout (bytes) ----------------
// row stride 36 floats = 144 B (bank-conflict-free fragment loads)
#define XROWB   144
#define HALF_SZ (128 * XROWB)        // 18432 (one of hi/lo)
#define STG_SZ  (2 * HALF_SZ)        // 36864 per stage per operand
#define SM_X0   0                    // X stages: [0, 73728)
#define SM_Y0   73728                // Y stages: [73728, 147456)
#define SM_SIM  147456               // 64 x 133 floats = 34048
#define SM_LV   181504               // 128*10*4 = 5120
#define SM_LI   186624               // 5120
#define SM_TOT  191744
#define SIMP    133

// ---------------- helpers ----------------
static __device__ __forceinline__ uint32_t cvta_s(const void* p) {
    return (uint32_t)__cvta_generic_to_shared(p);
}
static __device__ __forceinline__ uint32_t lds32(uint32_t a) {
    uint32_t v;
    asm volatile("ld.shared.b32 %0, [%1];" : "=r"(v) : "r"(a));
    return v;
}
static __device__ __forceinline__ void cp16(uint32_t d, const void* s) {
    asm volatile("cp.async.cg.shared.global [%0], [%1], 16;" :: "r"(d), "l"(s));
}
static __device__ __forceinline__ void cp_commit() { asm volatile("cp.async.commit_group;"); }
template <int N> static __device__ __forceinline__ void cp_wait() {
    asm volatile("cp.async.wait_group %0;" :: "n"(N));
}
static __device__ __forceinline__ void mma8(float* d, const uint32_t* a,
                                            uint32_t b0, uint32_t b1) {
    asm volatile(
        "mma.sync.aligned.m16n8k8.row.col.f32.tf32.tf32.f32 "
        "{%0,%1,%2,%3}, {%4,%5,%6,%7}, {%8,%9}, {%0,%1,%2,%3};"
        : "+f"(d[0]), "+f"(d[1]), "+f"(d[2]), "+f"(d[3])
        : "r"(a[0]), "r"(a[1]), "r"(a[2]), "r"(a[3]), "r"(b0), "r"(b1));
}
static __device__ __forceinline__ void split_tf32(float v, float& hi, float& lo) {
    uint32_t u;
    asm("cvt.rna.tf32.f32 %0, %1;" : "=r"(u) : "f"(v));
    hi = __uint_as_float(u);
    lo = v - hi;
}

// ---------------- kernel 1: normalize + tf32-split ----------------
__global__ void norm_split_kernel(const float* __restrict__ fx, const float* __restrict__ fy) {
    int wid  = (blockIdx.x * blockDim.x + threadIdx.x) >> 5;
    int lane = threadIdx.x & 31;
    const int totx = BB * NX;
    if (wid >= totx + BB * NY) return;
    const float* src; float *dhi, *dlo;
    if (wid < totx) {
        src = fx + (size_t)wid * DD;
        dhi = g_xhi + (size_t)wid * DD;  dlo = g_xlo + (size_t)wid * DD;
    } else {
        int r = wid - totx;
        src = fy + (size_t)r * DD;
        dhi = g_yhi + (size_t)r * DD;    dlo = g_ylo + (size_t)r * DD;
    }
    float4 a = ((const float4*)src)[lane];
    float4 b = ((const float4*)src)[lane + 32];
    float s = a.x*a.x + a.y*a.y + a.z*a.z + a.w*a.w
            + b.x*b.x + b.y*b.y + b.z*b.z + b.w*b.w;
#pragma unroll
    for (int off = 16; off > 0; off >>= 1) s += __shfl_xor_sync(0xffffffffu, s, off);
    float inv = 1.0f / fmaxf(sqrtf(s), 1e-12f);
    float4 hi0, lo0, hi1, lo1;
    split_tf32(a.x * inv, hi0.x, lo0.x);  split_tf32(a.y * inv, hi0.y, lo0.y);
    split_tf32(a.z * inv, hi0.z, lo0.z);  split_tf32(a.w * inv, hi0.w, lo0.w);
    split_tf32(b.x * inv, hi1.x, lo1.x);  split_tf32(b.y * inv, hi1.y, lo1.y);
    split_tf32(b.z * inv, hi1.z, lo1.z);  split_tf32(b.w * inv, hi1.w, lo1.w);
    ((float4*)dhi)[lane]      = hi0;  ((float4*)dhi)[lane + 32] = hi1;
    ((float4*)dlo)[lane]      = lo0;  ((float4*)dlo)[lane + 32] = lo1;
}

// ---------------- kernel 2: mma.sync 4xTF32 GEMM + fused top-k ----------------
extern __shared__ unsigned char smem_raw[];

__global__ void __launch_bounds__(NTHR, 1)
sim_mma_kernel(float* __restrict__ out, int out_size) {
    const int b    = blockIdx.y;
    const int xt   = blockIdx.x;
    const int tid  = threadIdx.x;
    const int wid  = tid >> 5, lane = tid & 31;
    const int warpM = wid & 3;           // 4 warps along M (32 rows each)
    const int warpN = wid >> 2;          // 4 warps along N (32 cols each)
    const int gid  = lane >> 2;          // 0..7
    const int tig  = lane & 3;           // 0..3

    uint32_t s0 = cvta_s(smem_raw);
    float* SIM = (float*)(smem_raw + SM_SIM);
    float* LV  = (float*)(smem_raw + SM_LV);
    int*   LI  = (int*)(smem_raw + SM_LI);

    for (int i = tid; i < TMR * KK; i += NTHR) { LV[i] = -1e38f; LI[i] = 0; }
    __syncthreads();

    const float* xbh = g_xhi + ((size_t)b * NX + (size_t)xt * TMR) * DD;
    const float* xbl = g_xlo + ((size_t)b * NX + (size_t)xt * TMR) * DD;
    const float* ybh = g_yhi + (size_t)b * NY * DD;
    const float* ybl = g_ylo + (size_t)b * NY * DD;

    // per-thread cp.async slots: 2 units per half (1024 units per 128x32 half)
    int frow[2], fq[2]; uint32_t foff[2];
#pragma unroll
    for (int i = 0; i < 2; i++) {
        int u = i * NTHR + tid;
        frow[i] = u >> 3; fq[i] = u & 7;
        foff[i] = (uint32_t)(frow[i] * XROWB + fq[i] * 16);
    }

    // fragment base byte offsets (within a 128x36f half)
    uint32_t aoff[2], boff[4];
#pragma unroll
    for (int m = 0; m < 2; m++)
        aoff[m] = (uint32_t)((warpM * 32 + m * 16 + gid) * XROWB + tig * 4);
#pragma unroll
    for (int n = 0; n < 4; n++)
        boff[n] = (uint32_t)((warpN * 32 + n * 8 + gid) * XROWB + tig * 4);

    float acc[2][4][4];

    // prologue: fill chunk 0 -> stage 0
    {
#pragma unroll
        for (int i = 0; i < 2; i++) {
            int so = frow[i] * DD + fq[i] * 4;
            cp16(s0 + SM_X0 + foff[i],           xbh + so);
            cp16(s0 + SM_X0 + HALF_SZ + foff[i], xbl + so);
            cp16(s0 + SM_Y0 + foff[i],           ybh + so);
            cp16(s0 + SM_Y0 + HALF_SZ + foff[i], ybl + so);
        }
        cp_commit();
    }

    for (int cc = 0; cc < CHTOT; cc++) {
        const int buf = cc & 1;
        const int c = cc & 7, t = cc >> 3;

        if (cc + 1 < CHTOT) {
            int nb = (cc + 1) & 1;
            int tn = (cc + 1) >> 3, cn = (cc + 1) & 7;
            int koff = cn * KCH;
            const float* xh = xbh + koff;
            const float* xl = xbl + koff;
            const float* yh = ybh + (size_t)tn * TNC * DD + koff;
            const float* yl = ybl + (size_t)tn * TNC * DD + koff;
            uint32_t xs = s0 + SM_X0 + (uint32_t)(nb * STG_SZ);
            uint32_t ys = s0 + SM_Y0 + (uint32_t)(nb * STG_SZ);
#pragma unroll
            for (int i = 0; i < 2; i++) {
                int so = frow[i] * DD + fq[i] * 4;
                cp16(xs + foff[i],           xh + so);
                cp16(xs + HALF_SZ + foff[i], xl + so);
                cp16(ys + foff[i],           yh + so);
                cp16(ys + HALF_SZ + foff[i], yl + so);
            }
            cp_commit();
            cp_wait<1>();
        } else {
            cp_wait<0>();
        }
        __syncthreads();

        if (c == 0) {
#pragma unroll
            for (int m = 0; m < 2; m++)
#pragma unroll
                for (int n = 0; n < 4; n++)
#pragma unroll
                    for (int j = 0; j < 4; j++) acc[m][n][j] = 0.0f;
        }

        const uint32_t xs = s0 + SM_X0 + (uint32_t)(buf * STG_SZ);
        const uint32_t ys = s0 + SM_Y0 + (uint32_t)(buf * STG_SZ);

        // 4 passes: Ah*Bh, Ah*Bl, Al*Bh, Al*Bl  (full fp32-accuracy split)
#pragma unroll
        for (int pass = 0; pass < 4; pass++) {
            const uint32_t A  = xs + ((pass >= 2) ? HALF_SZ : 0u);
            const uint32_t Bb = ys + ((pass & 1) ? HALF_SZ : 0u);
#pragma unroll
            for (int ks = 0; ks < 4; ks++) {
                const uint32_t kb = (uint32_t)(ks * 32);   // 8 floats
                uint32_t afr[2][4];
#pragma unroll
                for (int m = 0; m < 2; m++) {
                    afr[m][0] = lds32(A + aoff[m] + kb);
                    afr[m][1] = lds32(A + aoff[m] + kb + 8 * XROWB);
                    afr[m][2] = lds32(A + aoff[m] + kb + 16);
                    afr[m][3] = lds32(A + aoff[m] + kb + 8 * XROWB + 16);
                }
                uint32_t b0[4], b1[4];
#pragma unroll
                for (int n = 0; n < 4; n++) {
                    b0[n] = lds32(Bb + boff[n] + kb);
                    b1[n] = lds32(Bb + boff[n] + kb + 16);
                }
#pragma unroll
                for (int m = 0; m < 2; m++)
#pragma unroll
                    for (int n = 0; n < 4; n++)
                        mma8(acc[m][n], afr[m], b0[n], b1[n]);
            }
        }
        __syncthreads();

        // tile complete: stage SIM halves (64 rows each) + top-k scan
        if (c == 7) {
            const int col0 = t * TNC;
#pragma unroll
            for (int h = 0; h < 2; h++) {
                if ((warpM >> 1) == h) {
#pragma unroll
                    for (int m = 0; m < 2; m++) {
                        int r0 = (warpM & 1) * 32 + m * 16 + gid;
#pragma unroll
                        for (int n = 0; n < 4; n++) {
                            int col = warpN * 32 + n * 8 + 2 * tig;
                            SIM[r0 * SIMP + col]           = acc[m][n][0];
                            SIM[r0 * SIMP + col + 1]       = acc[m][n][1];
                            SIM[(r0 + 8) * SIMP + col]     = acc[m][n][2];
                            SIM[(r0 + 8) * SIMP + col + 1] = acc[m][n][3];
                        }
                    }
                }
                __syncthreads();
                if (tid < 64) {
                    int row = h * 64 + tid;
                    float* lv = LV + row * KK;
                    int*   li = LI + row * KK;
                    const float* srow = SIM + tid * SIMP;
                    float lv9 = lv[KK - 1];
#pragma unroll 4
                    for (int cL = 0; cL < TNC; cL++) {
                        float vv = srow[cL];
                        if (vv > lv9) {
                            int p = KK - 1;
                            while (p > 0 && lv[p - 1] < vv) {
                                lv[p] = lv[p - 1]; li[p] = li[p - 1]; --p;
                            }
                            lv[p] = vv; li[p] = col0 + cL;
                            lv9 = lv[KK - 1];
                        }
                    }
                }
                __syncthreads();
            }
        }
    }

    // ---- finalize: softmax + sort-by-col + write ----
    if (tid < TMR) {
        float v[KK]; int ix[KK];
#pragma unroll
        for (int k = 0; k < KK; k++) { v[k] = LV[tid * KK + k]; ix[k] = LI[tid * KK + k]; }
        float m = v[0];
        float e[KK]; float ssum = 0.0f;
#pragma unroll
        for (int k = 0; k < KK; k++) { e[k] = expf((v[k] - m) * INV_TAU); ssum += e[k]; }
        float inv = 1.0f / ssum;
#pragma unroll
        for (int a = 1; a < KK; a++) {
            int ki = ix[a]; float ke = e[a]; int p = a;
            while (p > 0 && ix[p - 1] > ki) { ix[p] = ix[p - 1]; e[p] = e[p - 1]; --p; }
            ix[p] = ki; e[p] = ke;
        }
        int gRow = xt * TMR + tid;
        size_t basev = ((size_t)b * NX + gRow) * KK;
        bool write_idx = (out_size >= 4 * NVAL);
#pragma unroll
        for (int k = 0; k < KK; k++) {
            out[basev + k] = e[k] * inv;
            if (write_idx) {
                out[(size_t)NVAL     + basev + k] = (float)b;
                out[(size_t)2 * NVAL + basev + k] = (float)gRow;
                out[(size_t)3 * NVAL + basev + k] = (float)ix[k];
            }
        }
    }
}

// ---------------- launch ----------------
extern "C" void kernel_launch(void* const* d_in, const int* in_sizes, int n_in,
                              void* d_out, int out_size) {
    const float* fx = (const float*)d_in[0];
    const float* fy = (const float*)d_in[1];
    float* out = (float*)d_out;

    int nrows = BB * NX + BB * NY;             // warp per row
    norm_split_kernel<<<(nrows + 7) / 8, 256>>>(fx, fy);

    cudaFuncSetAttribute(sim_mma_kernel,
                         cudaFuncAttributeMaxDynamicSharedMemorySize, SM_TOT);
    dim3 g2(NX / TMR, BB);                     // 32 x 4 = 128 CTAs
    sim_mma_kernel<<<g2, NTHR, SM_TOT>>>(out, out_size);
}

// round 9
// speedup vs baseline: 1.2773x; 1.2773x over previous
#include <cuda_runtime.h>
#include <cstdint>
#include <math.h>

// ---------------- problem constants ----------------
#define BB   4
#define NX   4096
#define NY   8192
#define DD   256
#define TMR  128                 // x rows per CTA
#define TNC  128                 // y cols per tile
#define KCH  32                  // k per chunk
#define NTIL (NY / TNC)          // 64 y tiles
#define NCHK (DD / KCH)          // 8 chunks per tile
#define CHTOT (NTIL * NCHK)      // 512 chunk iterations
#define KK   10
#define NVAL (BB * NX * KK)      // 163840
#define INV_TAU 20.0f
#define NTHR 512
#define BLKF 4096                // floats per 16KB block (128 rows x 32 k)

// blocked + swizzled tf32-split scratch:
// block index: X: ((b*32+xt)*8+c), Y: ((b*64+t)*8+c); within block:
// float4 slot = row*8 + ((q ^ (row&7))), q = (k_in_32)>>2
__device__ float g_xhi[(size_t)BB * NX * DD];
__device__ float g_xlo[(size_t)BB * NX * DD];
__device__ float g_yhi[(size_t)BB * NY * DD];
__device__ float g_ylo[(size_t)BB * NY * DD];

// ---------------- smem layout (bytes) ----------------
// stage s at s*65536: Xhi 16K | Xlo 16K | Yhi 16K | Ylo 16K
#define STG_SZ  65536
#define OFF_XHI 0
#define OFF_XLO 16384
#define OFF_YHI 32768
#define OFF_YLO 49152
#define SM_SIM  131072               // 64 x 133 floats = 34048
#define SM_LV   165120               // 128*10*4
#define SM_LI   170240
#define SM_CTRL 175360               // mb0 @+0, mb1 @+8
#define SM_TOT  175424
#define SIMP    133

// ---------------- helpers ----------------
static __device__ __forceinline__ uint32_t cvta_s(const void* p) {
    return (uint32_t)__cvta_generic_to_shared(p);
}
static __device__ __forceinline__ uint32_t lds32(uint32_t a) {
    uint32_t v;
    asm volatile("ld.shared.b32 %0, [%1];" : "=r"(v) : "r"(a));
    return v;
}
static __device__ __forceinline__ void bulk16k(uint32_t dst, const void* src, uint32_t mbar) {
    asm volatile(
        "cp.async.bulk.shared::cta.global.mbarrier::complete_tx::bytes [%0], [%1], %2, [%3];"
        :: "r"(dst), "l"(src), "r"(16384u), "r"(mbar) : "memory");
}
static __device__ __forceinline__ void mb_init(uint32_t a, uint32_t c) {
    asm volatile("mbarrier.init.shared.b64 [%0], %1;" :: "r"(a), "r"(c) : "memory");
}
static __device__ __forceinline__ void mb_expect(uint32_t a, uint32_t bytes) {
    asm volatile("mbarrier.arrive.expect_tx.shared.b64 _, [%0], %1;" :: "r"(a), "r"(bytes) : "memory");
}
static __device__ __forceinline__ void mb_wait(uint32_t a, uint32_t par) {
    asm volatile(
        "{\n\t.reg .pred P;\n\t"
        "WL%=:\n\t"
        "mbarrier.try_wait.parity.acquire.cta.shared::cta.b64 P, [%0], %1, 0x989680;\n\t"
        "@P bra WD%=;\n\t"
        "bra WL%=;\n\t"
        "WD%=:\n\t}"
        :: "r"(a), "r"(par) : "memory");
}
static __device__ __forceinline__ void mma8(float* d, const uint32_t* a,
                                            uint32_t b0, uint32_t b1) {
    asm volatile(
        "mma.sync.aligned.m16n8k8.row.col.f32.tf32.tf32.f32 "
        "{%0,%1,%2,%3}, {%4,%5,%6,%7}, {%8,%9}, {%0,%1,%2,%3};"
        : "+f"(d[0]), "+f"(d[1]), "+f"(d[2]), "+f"(d[3])
        : "r"(a[0]), "r"(a[1]), "r"(a[2]), "r"(a[3]), "r"(b0), "r"(b1));
}
static __device__ __forceinline__ void split_tf32(float v, float& hi, float& lo) {
    uint32_t u;
    asm("cvt.rna.tf32.f32 %0, %1;" : "=r"(u) : "f"(v));
    hi = __uint_as_float(u);
    lo = v - hi;
}

// ---------------- kernel 1: normalize + split + blocked/swizzled store ----------------
__global__ void norm_split_kernel(const float* __restrict__ fx, const float* __restrict__ fy) {
    int wid  = (blockIdx.x * blockDim.x + threadIdx.x) >> 5;
    int lane = threadIdx.x & 31;
    const int totx = BB * NX;
    if (wid >= totx + BB * NY) return;

    const float* src;
    float *dhi, *dlo;
    int blk0, rit;
    if (wid < totx) {
        int b = wid / NX, r = wid % NX;
        src = fx + (size_t)wid * DD;
        dhi = g_xhi; dlo = g_xlo;
        blk0 = (b * 32 + (r >> 7)) * 8;     // chunk 0 block for this x tile
        rit = r & 127;
    } else {
        int r0 = wid - totx;
        int b = r0 / NY, r = r0 % NY;
        src = fy + (size_t)r0 * DD;
        dhi = g_yhi; dlo = g_ylo;
        blk0 = (b * 64 + (r >> 7)) * 8;
        rit = r & 127;
    }
    float4 a = ((const float4*)src)[lane];
    float4 b4 = ((const float4*)src)[lane + 32];
    float s = a.x*a.x + a.y*a.y + a.z*a.z + a.w*a.w
            + b4.x*b4.x + b4.y*b4.y + b4.z*b4.z + b4.w*b4.w;
#pragma unroll
    for (int off = 16; off > 0; off >>= 1) s += __shfl_xor_sync(0xffffffffu, s, off);
    float inv = 1.0f / fmaxf(sqrtf(s), 1e-12f);

    float4 hi0, lo0, hi1, lo1;
    split_tf32(a.x * inv, hi0.x, lo0.x);  split_tf32(a.y * inv, hi0.y, lo0.y);
    split_tf32(a.z * inv, hi0.z, lo0.z);  split_tf32(a.w * inv, hi0.w, lo0.w);
    split_tf32(b4.x * inv, hi1.x, lo1.x); split_tf32(b4.y * inv, hi1.y, lo1.y);
    split_tf32(b4.z * inv, hi1.z, lo1.z); split_tf32(b4.w * inv, hi1.w, lo1.w);

    // lane holds k = 4*lane..4*lane+3 (chunk lane>>3) and k+128 (chunk 4+lane>>3)
    int q = lane & 7;
    int unit = q ^ (rit & 7);
    size_t slot0 = ((size_t)(blk0 + (lane >> 3)) * 1024) + rit * 8 + unit;      // float4 units
    size_t slot1 = ((size_t)(blk0 + 4 + (lane >> 3)) * 1024) + rit * 8 + unit;
    ((float4*)dhi)[slot0] = hi0;  ((float4*)dhi)[slot1] = hi1;
    ((float4*)dlo)[slot0] = lo0;  ((float4*)dlo)[slot1] = lo1;
}

// ---------------- kernel 2: bulk-fed mma.sync 3xTF32 GEMM + fused top-k ----------------
extern __shared__ unsigned char smem_raw[];

__global__ void __launch_bounds__(NTHR, 1)
sim_mma_kernel(float* __restrict__ out, int out_size) {
    const int b    = blockIdx.y;
    const int xt   = blockIdx.x;
    const int tid  = threadIdx.x;
    const int wid  = tid >> 5, lane = tid & 31;
    const int warpM = wid & 3;           // 4 warps along M (32 rows each)
    const int warpN = wid >> 2;          // 4 warps along N (32 cols each)
    const int gid  = lane >> 2;          // 0..7
    const int tig  = lane & 3;           // 0..3

    uint32_t s0 = cvta_s(smem_raw);
    float* SIM = (float*)(smem_raw + SM_SIM);
    float* LV  = (float*)(smem_raw + SM_LV);
    int*   LI  = (int*)(smem_raw + SM_LI);
    const uint32_t mb0 = s0 + SM_CTRL, mb1 = s0 + SM_CTRL + 8;

    for (int i = tid; i < TMR * KK; i += NTHR) { LV[i] = -1e38f; LI[i] = 0; }
    if (tid == 0) { mb_init(mb0, 1); mb_init(mb1, 1); }
    __syncthreads();

    const int xblk0 = (b * 32 + xt) * 8;        // x blocks: xblk0 + c
    const int yblk0 = b * 64 * 8;               // y blocks: yblk0 + t*8 + c

    // fragment addressing (within one 128x128B swizzled half)
    // A: row = warpM*32 + m*16 + gid (+8); unit = (2ks+h) ^ (row&7); +tig*4
    uint32_t abase = (uint32_t)((warpM * 32 + gid) * 128 + tig * 4);
    const uint32_t arsw = (uint32_t)(gid & 7);
    uint32_t bbase[4];
#pragma unroll
    for (int n = 0; n < 4; n++)
        bbase[n] = (uint32_t)((warpN * 32 + n * 8 + gid) * 128 + tig * 4);
    const uint32_t brsw = (uint32_t)(gid & 7);

    float acc[2][4][4];

    // prologue: fill chunk 0 -> stage 0
    if (tid == 0) {
        mb_expect(mb0, 65536);
        bulk16k(s0 + OFF_XHI, g_xhi + (size_t)xblk0 * BLKF, mb0);
        bulk16k(s0 + OFF_XLO, g_xlo + (size_t)xblk0 * BLKF, mb0);
        bulk16k(s0 + OFF_YHI, g_yhi + (size_t)yblk0 * BLKF, mb0);
        bulk16k(s0 + OFF_YLO, g_ylo + (size_t)yblk0 * BLKF, mb0);
    }

    for (int cc = 0; cc < CHTOT; cc++) {
        const int buf = cc & 1;
        const int c = cc & 7, t = cc >> 3;

        // issue fill for cc+1 into the other stage (free since end of cc-1)
        if (cc + 1 < CHTOT && tid == 0) {
            int nb = (cc + 1) & 1;
            int tn = (cc + 1) >> 3, cn = (cc + 1) & 7;
            uint32_t sb = s0 + (uint32_t)(nb * STG_SZ);
            uint32_t mbn = nb ? mb1 : mb0;
            mb_expect(mbn, 65536);
            bulk16k(sb + OFF_XHI, g_xhi + (size_t)(xblk0 + cn) * BLKF, mbn);
            bulk16k(sb + OFF_XLO, g_xlo + (size_t)(xblk0 + cn) * BLKF, mbn);
            bulk16k(sb + OFF_YHI, g_yhi + (size_t)(yblk0 + tn * 8 + cn) * BLKF, mbn);
            bulk16k(sb + OFF_YLO, g_ylo + (size_t)(yblk0 + tn * 8 + cn) * BLKF, mbn);
        }

        // wait for this chunk's data
        mb_wait(buf ? mb1 : mb0, (uint32_t)((cc >> 1) & 1));

        if (c == 0) {
#pragma unroll
            for (int m = 0; m < 2; m++)
#pragma unroll
                for (int n = 0; n < 4; n++)
#pragma unroll
                    for (int j = 0; j < 4; j++) acc[m][n][j] = 0.0f;
        }

        const uint32_t sb = s0 + (uint32_t)(buf * STG_SZ);

        // 3 passes: Ah*Bh, Ah*Bl, Al*Bh
#pragma unroll
        for (int pass = 0; pass < 3; pass++) {
            const uint32_t A  = sb + ((pass == 2) ? OFF_XLO : OFF_XHI);
            const uint32_t Bb = sb + ((pass == 1) ? OFF_YLO : OFF_YHI);
#pragma unroll
            for (int ks = 0; ks < 4; ks++) {
                const uint32_t u0 = (uint32_t)((2 * ks) ^ arsw) << 4;
                const uint32_t u1 = (uint32_t)((2 * ks + 1) ^ arsw) << 4;
                uint32_t afr[2][4];
#pragma unroll
                for (int m = 0; m < 2; m++) {
                    uint32_t ab = A + abase + (uint32_t)(m * 16 * 128);
                    afr[m][0] = lds32(ab + u0);
                    afr[m][1] = lds32(ab + 8 * 128 + u0);
                    afr[m][2] = lds32(ab + u1);
                    afr[m][3] = lds32(ab + 8 * 128 + u1);
                }
                const uint32_t v0 = (uint32_t)((2 * ks) ^ brsw) << 4;
                const uint32_t v1 = (uint32_t)((2 * ks + 1) ^ brsw) << 4;
                uint32_t b0[4], b1[4];
#pragma unroll
                for (int n = 0; n < 4; n++) {
                    b0[n] = lds32(Bb + bbase[n] + v0);
                    b1[n] = lds32(Bb + bbase[n] + v1);
                }
#pragma unroll
                for (int m = 0; m < 2; m++)
#pragma unroll
                    for (int n = 0; n < 4; n++)
                        mma8(acc[m][n], afr[m], b0[n], b1[n]);
            }
        }
        __syncthreads();   // all reads of stage `buf` done -> refillable next iter

        // tile complete: stage SIM halves (64 rows each) + top-k scan
        if (c == 7) {
            const int col0 = t * TNC;
#pragma unroll
            for (int h = 0; h < 2; h++) {
                if ((warpM >> 1) == h) {
#pragma unroll
                    for (int m = 0; m < 2; m++) {
                        int r0 = (warpM & 1) * 32 + m * 16 + gid;
#pragma unroll
                        for (int n = 0; n < 4; n++) {
                            int col = warpN * 32 + n * 8 + 2 * tig;
                            SIM[r0 * SIMP + col]           = acc[m][n][0];
                            SIM[r0 * SIMP + col + 1]       = acc[m][n][1];
                            SIM[(r0 + 8) * SIMP + col]     = acc[m][n][2];
                            SIM[(r0 + 8) * SIMP + col + 1] = acc[m][n][3];
                        }
                    }
                }
                __syncthreads();
                if (tid < 64) {
                    int row = h * 64 + tid;
                    float* lv = LV + row * KK;
                    int*   li = LI + row * KK;
                    const float* srow = SIM + tid * SIMP;
                    float lv9 = lv[KK - 1];
#pragma unroll 4
                    for (int cL = 0; cL < TNC; cL++) {
                        float vv = srow[cL];
                        if (vv > lv9) {
                            int p = KK - 1;
                            while (p > 0 && lv[p - 1] < vv) {
                                lv[p] = lv[p - 1]; li[p] = li[p - 1]; --p;
                            }
                            lv[p] = vv; li[p] = col0 + cL;
                            lv9 = lv[KK - 1];
                        }
                    }
                }
                __syncthreads();
            }
        }
    }

    // ---- finalize: softmax + sort-by-col + write ----
    if (tid < TMR) {
        float v[KK]; int ix[KK];
#pragma unroll
        for (int k = 0; k < KK; k++) { v[k] = LV[tid * KK + k]; ix[k] = LI[tid * KK + k]; }
        float m = v[0];
        float e[KK]; float ssum = 0.0f;
#pragma unroll
        for (int k = 0; k < KK; k++) { e[k] = expf((v[k] - m) * INV_TAU); ssum += e[k]; }
        float inv = 1.0f / ssum;
#pragma unroll
        for (int a = 1; a < KK; a++) {
            int ki = ix[a]; float ke = e[a]; int p = a;
            while (p > 0 && ix[p - 1] > ki) { ix[p] = ix[p - 1]; e[p] = e[p - 1]; --p; }
            ix[p] = ki; e[p] = ke;
        }
        int gRow = xt * TMR + tid;
        size_t basev = ((size_t)b * NX + gRow) * KK;
        bool write_idx = (out_size >= 4 * NVAL);
#pragma unroll
        for (int k = 0; k < KK; k++) {
            out[basev + k] = e[k] * inv;
            if (write_idx) {
                out[(size_t)NVAL     + basev + k] = (float)b;
                out[(size_t)2 * NVAL + basev + k] = (float)gRow;
                out[(size_t)3 * NVAL + basev + k] = (float)ix[k];
            }
        }
    }
}

// ---------------- launch ----------------
extern "C" void kernel_launch(void* const* d_in, const int* in_sizes, int n_in,
                              void* d_out, int out_size) {
    const float* fx = (const float*)d_in[0];
    const float* fy = (const float*)d_in[1];
    float* out = (float*)d_out;

    int nrows = BB * NX + BB * NY;             // warp per row
    norm_split_kernel<<<(nrows + 7) / 8, 256>>>(fx, fy);

    cudaFuncSetAttribute(sim_mma_kernel,
                         cudaFuncAttributeMaxDynamicSharedMemorySize, SM_TOT);
    dim3 g2(NX / TMR, BB);                     // 32 x 4 = 128 CTAs
    sim_mma_kernel<<<g2, NTHR, SM_TOT>>>(out, out_size);
}

// round 10
// speedup vs baseline: 1.3380x; 1.0475x over previous
#include <cuda_runtime.h>
#include <cstdint>
#include <math.h>

// ---------------- problem constants ----------------
#define BB   4
#define NX   4096
#define NY   8192
#define DD   256
#define TMR  128                 // x rows per CTA
#define TNC  128                 // y cols per tile
#define KCH  32                  // k per chunk
#define NTIL (NY / TNC)          // 64 y tiles
#define NCHK (DD / KCH)          // 8 chunks per tile
#define CHTOT (NTIL * NCHK)      // 512 chunk iterations
#define KK   10
#define NVAL (BB * NX * KK)      // 163840
#define INV_TAU 20.0f
#define NTHR 512
#define BLKF 4096                // floats per 16KB block (128 rows x 32 k)

// blocked + swizzled tf32-split scratch (same layout as R9)
__device__ __align__(128) float g_xhi[(size_t)BB * NX * DD];
__device__ __align__(128) float g_xlo[(size_t)BB * NX * DD];
__device__ __align__(128) float g_yhi[(size_t)BB * NY * DD];
__device__ __align__(128) float g_ylo[(size_t)BB * NY * DD];

// ---------------- smem layout (bytes) ----------------
#define STG_SZ  65536
#define OFF_XHI 0
#define OFF_XLO 16384
#define OFF_YHI 32768
#define OFF_YLO 49152
#define SM_SIM  131072               // 64 x 133 floats = 34048
#define SM_LV   165120               // 128*10*4
#define SM_LI   170240
#define SM_CTRL 175360               // full0,full1,free0,free1 @ +0,+8,+16,+24
#define SM_TOT  175424
#define SIMP    133

// ---------------- helpers ----------------
static __device__ __forceinline__ uint32_t cvta_s(const void* p) {
    return (uint32_t)__cvta_generic_to_shared(p);
}
static __device__ __forceinline__ uint32_t lds32(uint32_t a) {
    uint32_t v;
    asm volatile("ld.shared.b32 %0, [%1];" : "=r"(v) : "r"(a));
    return v;
}
static __device__ __forceinline__ void bulk16k(uint32_t dst, const void* src, uint32_t mbar) {
    asm volatile(
        "cp.async.bulk.shared::cta.global.mbarrier::complete_tx::bytes [%0], [%1], %2, [%3];"
        :: "r"(dst), "l"(src), "r"(16384u), "r"(mbar) : "memory");
}
static __device__ __forceinline__ void mb_init(uint32_t a, uint32_t c) {
    asm volatile("mbarrier.init.shared.b64 [%0], %1;" :: "r"(a), "r"(c) : "memory");
}
static __device__ __forceinline__ void mb_expect(uint32_t a, uint32_t bytes) {
    asm volatile("mbarrier.arrive.expect_tx.shared.b64 _, [%0], %1;" :: "r"(a), "r"(bytes) : "memory");
}
static __device__ __forceinline__ void mb_arrive(uint32_t a) {
    asm volatile("mbarrier.arrive.shared.b64 _, [%0];" :: "r"(a) : "memory");
}
static __device__ __forceinline__ void mb_wait(uint32_t a, uint32_t par) {
    asm volatile(
        "{\n\t.reg .pred P;\n\t"
        "WL%=:\n\t"
        "mbarrier.try_wait.parity.acquire.cta.shared::cta.b64 P, [%0], %1, 0x989680;\n\t"
        "@P bra WD%=;\n\t"
        "bra WL%=;\n\t"
        "WD%=:\n\t}"
        :: "r"(a), "r"(par) : "memory");
}
static __device__ __forceinline__ void mma8(float* d, const uint32_t* a,
                                            uint32_t b0, uint32_t b1) {
    asm volatile(
        "mma.sync.aligned.m16n8k8.row.col.f32.tf32.tf32.f32 "
        "{%0,%1,%2,%3}, {%4,%5,%6,%7}, {%8,%9}, {%0,%1,%2,%3};"
        : "+f"(d[0]), "+f"(d[1]), "+f"(d[2]), "+f"(d[3])
        : "r"(a[0]), "r"(a[1]), "r"(a[2]), "r"(a[3]), "r"(b0), "r"(b1));
}
static __device__ __forceinline__ void split_tf32(float v, float& hi, float& lo) {
    uint32_t u;
    asm("cvt.rna.tf32.f32 %0, %1;" : "=r"(u) : "f"(v));
    hi = __uint_as_float(u);
    lo = v - hi;
}

// ---------------- kernel 1: normalize + split + blocked/swizzled store ----------------
__global__ void norm_split_kernel(const float* __restrict__ fx, const float* __restrict__ fy) {
    int wid  = (blockIdx.x * blockDim.x + threadIdx.x) >> 5;
    int lane = threadIdx.x & 31;
    const int totx = BB * NX;
    if (wid >= totx + BB * NY) return;

    const float* src;
    float *dhi, *dlo;
    int blk0, rit;
    if (wid < totx) {
        int b = wid / NX, r = wid % NX;
        src = fx + (size_t)wid * DD;
        dhi = g_xhi; dlo = g_xlo;
        blk0 = (b * 32 + (r >> 7)) * 8;
        rit = r & 127;
    } else {
        int r0 = wid - totx;
        int b = r0 / NY, r = r0 % NY;
        src = fy + (size_t)r0 * DD;
        dhi = g_yhi; dlo = g_ylo;
        blk0 = (b * 64 + (r >> 7)) * 8;
        rit = r & 127;
    }
    float4 a = ((const float4*)src)[lane];
    float4 b4 = ((const float4*)src)[lane + 32];
    float s = a.x*a.x + a.y*a.y + a.z*a.z + a.w*a.w
            + b4.x*b4.x + b4.y*b4.y + b4.z*b4.z + b4.w*b4.w;
#pragma unroll
    for (int off = 16; off > 0; off >>= 1) s += __shfl_xor_sync(0xffffffffu, s, off);
    float inv = 1.0f / fmaxf(sqrtf(s), 1e-12f);

    float4 hi0, lo0, hi1, lo1;
    split_tf32(a.x * inv, hi0.x, lo0.x);  split_tf32(a.y * inv, hi0.y, lo0.y);
    split_tf32(a.z * inv, hi0.z, lo0.z);  split_tf32(a.w * inv, hi0.w, lo0.w);
    split_tf32(b4.x * inv, hi1.x, lo1.x); split_tf32(b4.y * inv, hi1.y, lo1.y);
    split_tf32(b4.z * inv, hi1.z, lo1.z); split_tf32(b4.w * inv, hi1.w, lo1.w);

    int q = lane & 7;
    int unit = q ^ (rit & 7);
    size_t slot0 = ((size_t)(blk0 + (lane >> 3)) * 1024) + rit * 8 + unit;
    size_t slot1 = ((size_t)(blk0 + 4 + (lane >> 3)) * 1024) + rit * 8 + unit;
    ((float4*)dhi)[slot0] = hi0;  ((float4*)dhi)[slot1] = hi1;
    ((float4*)dlo)[slot0] = lo0;  ((float4*)dlo)[slot1] = lo1;
}

// ---------------- kernel 2: bulk-fed mma.sync 3xTF32 GEMM + fused top-k ----------------
extern __shared__ unsigned char smem_raw[];

__global__ void __launch_bounds__(NTHR, 1)
sim_mma_kernel(float* __restrict__ out, int out_size) {
    const int b    = blockIdx.y;
    const int xt   = blockIdx.x;
    const int tid  = threadIdx.x;
    const int wid  = tid >> 5, lane = tid & 31;
    const int warpM = wid & 3;
    const int warpN = wid >> 2;
    const int gid  = lane >> 2;
    const int tig  = lane & 3;

    uint32_t s0 = cvta_s(smem_raw);
    float* SIM = (float*)(smem_raw + SM_SIM);
    float* LV  = (float*)(smem_raw + SM_LV);
    int*   LI  = (int*)(smem_raw + SM_LI);
    const uint32_t full0 = s0 + SM_CTRL,      full1 = s0 + SM_CTRL + 8;
    const uint32_t free0 = s0 + SM_CTRL + 16, free1 = s0 + SM_CTRL + 24;

    for (int i = tid; i < TMR * KK; i += NTHR) { LV[i] = -1e38f; LI[i] = 0; }
    if (tid == 0) {
        mb_init(full0, 1); mb_init(full1, 1);
        mb_init(free0, 16); mb_init(free1, 16);
    }
    __syncthreads();

    const int xblk0 = (b * 32 + xt) * 8;
    const int yblk0 = b * 64 * 8;

    uint32_t abase = (uint32_t)((warpM * 32 + gid) * 128 + tig * 4);
    const uint32_t arsw = (uint32_t)(gid & 7);
    uint32_t bbase[4];
#pragma unroll
    for (int n = 0; n < 4; n++)
        bbase[n] = (uint32_t)((warpN * 32 + n * 8 + gid) * 128 + tig * 4);
    const uint32_t brsw = (uint32_t)(gid & 7);

    float acc[2][4][4];

    // prologue: fill chunk 0 -> stage 0
    if (tid == 0) {
        mb_expect(full0, 65536);
        bulk16k(s0 + OFF_XHI, g_xhi + (size_t)xblk0 * BLKF, full0);
        bulk16k(s0 + OFF_XLO, g_xlo + (size_t)xblk0 * BLKF, full0);
        bulk16k(s0 + OFF_YHI, g_yhi + (size_t)yblk0 * BLKF, full0);
        bulk16k(s0 + OFF_YLO, g_ylo + (size_t)yblk0 * BLKF, full0);
    }

    for (int cc = 0; cc < CHTOT; cc++) {
        const int buf = cc & 1;
        const int c = cc & 7, t = cc >> 3;

        // wait for this chunk's data
        mb_wait(buf ? full1 : full0, (uint32_t)((cc >> 1) & 1));

        // producer: fill cc+1 into the other stage once it's been freed
        if (cc + 1 < CHTOT && tid == 0) {
            int nb = (cc + 1) & 1;
            int fi = (cc + 1) >> 1;              // fill instance of stage nb
            if (fi >= 1) mb_wait(nb ? free1 : free0, (uint32_t)((fi - 1) & 1));
            int tn = (cc + 1) >> 3, cn = (cc + 1) & 7;
            uint32_t sb = s0 + (uint32_t)(nb * STG_SZ);
            uint32_t mbn = nb ? full1 : full0;
            mb_expect(mbn, 65536);
            bulk16k(sb + OFF_XHI, g_xhi + (size_t)(xblk0 + cn) * BLKF, mbn);
            bulk16k(sb + OFF_XLO, g_xlo + (size_t)(xblk0 + cn) * BLKF, mbn);
            bulk16k(sb + OFF_YHI, g_yhi + (size_t)(yblk0 + tn * 8 + cn) * BLKF, mbn);
            bulk16k(sb + OFF_YLO, g_ylo + (size_t)(yblk0 + tn * 8 + cn) * BLKF, mbn);
        }

        if (c == 0) {
#pragma unroll
            for (int m = 0; m < 2; m++)
#pragma unroll
                for (int n = 0; n < 4; n++)
#pragma unroll
                    for (int j = 0; j < 4; j++) acc[m][n][j] = 0.0f;
        }

        const uint32_t sb = s0 + (uint32_t)(buf * STG_SZ);

        // 3 passes: Ah*Bh, Ah*Bl, Al*Bh  (identical order/arithmetic to R9)
#pragma unroll
        for (int pass = 0; pass < 3; pass++) {
            const uint32_t A  = sb + ((pass == 2) ? OFF_XLO : OFF_XHI);
            const uint32_t Bb = sb + ((pass == 1) ? OFF_YLO : OFF_YHI);
#pragma unroll
            for (int ks = 0; ks < 4; ks++) {
                const uint32_t u0 = (uint32_t)((2 * ks) ^ arsw) << 4;
                const uint32_t u1 = (uint32_t)((2 * ks + 1) ^ arsw) << 4;
                uint32_t afr[2][4];
#pragma unroll
                for (int m = 0; m < 2; m++) {
                    uint32_t ab = A + abase + (uint32_t)(m * 16 * 128);
                    afr[m][0] = lds32(ab + u0);
                    afr[m][1] = lds32(ab + 8 * 128 + u0);
                    afr[m][2] = lds32(ab + u1);
                    afr[m][3] = lds32(ab + 8 * 128 + u1);
                }
                const uint32_t v0 = (uint32_t)((2 * ks) ^ brsw) << 4;
                const uint32_t v1 = (uint32_t)((2 * ks + 1) ^ brsw) << 4;
                uint32_t b0[4], b1[4];
#pragma unroll
                for (int n = 0; n < 4; n++) {
                    b0[n] = lds32(Bb + bbase[n] + v0);
                    b1[n] = lds32(Bb + bbase[n] + v1);
                }
#pragma unroll
                for (int m = 0; m < 2; m++)
#pragma unroll
                    for (int n = 0; n < 4; n++)
                        mma8(acc[m][n], afr[m], b0[n], b1[n]);
            }
        }

        // declare stage free (operands consumed at MMA issue) — no block barrier
        if (lane == 0) mb_arrive(buf ? free1 : free0);

        // tile complete: stage SIM halves (64 rows each) + top-k scan
        if (c == 7) {
            const int col0 = t * TNC;
#pragma unroll
            for (int h = 0; h < 2; h++) {
                if ((warpM >> 1) == h) {
#pragma unroll
                    for (int m = 0; m < 2; m++) {
                        int r0 = (warpM & 1) * 32 + m * 16 + gid;
#pragma unroll
                        for (int n = 0; n < 4; n++) {
                            int col = warpN * 32 + n * 8 + 2 * tig;
                            SIM[r0 * SIMP + col]           = acc[m][n][0];
                            SIM[r0 * SIMP + col + 1]       = acc[m][n][1];
                            SIM[(r0 + 8) * SIMP + col]     = acc[m][n][2];
                            SIM[(r0 + 8) * SIMP + col + 1] = acc[m][n][3];
                        }
                    }
                }
                __syncthreads();
                if (tid < 64) {
                    int row = h * 64 + tid;
                    float* lv = LV + row * KK;
                    int*   li = LI + row * KK;
                    const float* srow = SIM + tid * SIMP;
                    float lv9 = lv[KK - 1];
#pragma unroll 4
                    for (int cL = 0; cL < TNC; cL++) {
                        float vv = srow[cL];
                        if (vv > lv9) {
                            int p = KK - 1;
                            while (p > 0 && lv[p - 1] < vv) {
                                lv[p] = lv[p - 1]; li[p] = li[p - 1]; --p;
                            }
                            lv[p] = vv; li[p] = col0 + cL;
                            lv9 = lv[KK - 1];
                        }
                    }
                }
                __syncthreads();
            }
        }
    }

    // ---- finalize: softmax + sort-by-col + write ----
    if (tid < TMR) {
        float v[KK]; int ix[KK];
#pragma unroll
        for (int k = 0; k < KK; k++) { v[k] = LV[tid * KK + k]; ix[k] = LI[tid * KK + k]; }
        float m = v[0];
        float e[KK]; float ssum = 0.0f;
#pragma unroll
        for (int k = 0; k < KK; k++) { e[k] = expf((v[k] - m) * INV_TAU); ssum += e[k]; }
        float inv = 1.0f / ssum;
#pragma unroll
        for (int a = 1; a < KK; a++) {
            int ki = ix[a]; float ke = e[a]; int p = a;
            while (p > 0 && ix[p - 1] > ki) { ix[p] = ix[p - 1]; e[p] = e[p - 1]; --p; }
            ix[p] = ki; e[p] = ke;
        }
        int gRow = xt * TMR + tid;
        size_t basev = ((size_t)b * NX + gRow) * KK;
        bool write_idx = (out_size >= 4 * NVAL);
#pragma unroll
        for (int k = 0; k < KK; k++) {
            out[basev + k] = e[k] * inv;
            if (write_idx) {
                out[(size_t)NVAL     + basev + k] = (float)b;
                out[(size_t)2 * NVAL + basev + k] = (float)gRow;
                out[(size_t)3 * NVAL + basev + k] = (float)ix[k];
            }
        }
    }
}

// ---------------- launch ----------------
extern "C" void kernel_launch(void* const* d_in, const int* in_sizes, int n_in,
                              void* d_out, int out_size) {
    const float* fx = (const float*)d_in[0];
    const float* fy = (const float*)d_in[1];
    float* out = (float*)d_out;

    int nrows = BB * NX + BB * NY;
    norm_split_kernel<<<(nrows + 7) / 8, 256>>>(fx, fy);

    cudaFuncSetAttribute(sim_mma_kernel,
                         cudaFuncAttributeMaxDynamicSharedMemorySize, SM_TOT);
    dim3 g2(NX / TMR, BB);                     // 128 CTAs
    sim_mma_kernel<<<g2, NTHR, SM_TOT>>>(out, out_size);
}

// round 11
// speedup vs baseline: 1.3871x; 1.0367x over previous
#include <cuda_runtime.h>
#include <cstdint>
#include <math.h>

// ---------------- problem constants ----------------
#define BB   4
#define NX   4096
#define NY   8192
#define DD   256
#define TMR  128                 // x rows per CTA
#define TNC  128                 // y cols per tile
#define KCH  32                  // k per chunk
#define NTIL (NY / TNC)          // 64 y tiles
#define NCHK (DD / KCH)          // 8 chunks per tile
#define CHTOT (NTIL * NCHK)      // 512 chunk iterations
#define KK   10
#define NVAL (BB * NX * KK)      // 163840
#define INV_TAU 20.0f
#define NTHR 256
#define BLKF 4096                // floats per 16KB block (128 rows x 32 k)

// blocked + swizzled tf32-split scratch (same layout as R9/R10)
__device__ __align__(128) float g_xhi[(size_t)BB * NX * DD];
__device__ __align__(128) float g_xlo[(size_t)BB * NX * DD];
__device__ __align__(128) float g_yhi[(size_t)BB * NY * DD];
__device__ __align__(128) float g_ylo[(size_t)BB * NY * DD];

// ---------------- smem layout (bytes) ----------------
#define STG_SZ  65536
#define OFF_XHI 0
#define OFF_XLO 16384
#define OFF_YHI 32768
#define OFF_YLO 49152
#define SM_SIM  131072               // 64 x 133 floats = 34048
#define SM_LV   165120               // 128*10*4
#define SM_LI   170240
#define SM_CTRL 175360               // full0,full1,free0,free1 @ +0,+8,+16,+24
#define SM_TOT  175424
#define SIMP    133

// ---------------- helpers ----------------
static __device__ __forceinline__ uint32_t cvta_s(const void* p) {
    return (uint32_t)__cvta_generic_to_shared(p);
}
static __device__ __forceinline__ uint32_t lds32(uint32_t a) {
    uint32_t v;
    asm volatile("ld.shared.b32 %0, [%1];" : "=r"(v) : "r"(a));
    return v;
}
static __device__ __forceinline__ void bulk16k(uint32_t dst, const void* src, uint32_t mbar) {
    asm volatile(
        "cp.async.bulk.shared::cta.global.mbarrier::complete_tx::bytes [%0], [%1], %2, [%3];"
        :: "r"(dst), "l"(src), "r"(16384u), "r"(mbar) : "memory");
}
static __device__ __forceinline__ void mb_init(uint32_t a, uint32_t c) {
    asm volatile("mbarrier.init.shared.b64 [%0], %1;" :: "r"(a), "r"(c) : "memory");
}
static __device__ __forceinline__ void mb_expect(uint32_t a, uint32_t bytes) {
    asm volatile("mbarrier.arrive.expect_tx.shared.b64 _, [%0], %1;" :: "r"(a), "r"(bytes) : "memory");
}
static __device__ __forceinline__ void mb_arrive(uint32_t a) {
    asm volatile("mbarrier.arrive.shared.b64 _, [%0];" :: "r"(a) : "memory");
}
static __device__ __forceinline__ void mb_wait(uint32_t a, uint32_t par) {
    asm volatile(
        "{\n\t.reg .pred P;\n\t"
        "WL%=:\n\t"
        "mbarrier.try_wait.parity.acquire.cta.shared::cta.b64 P, [%0], %1, 0x989680;\n\t"
        "@P bra WD%=;\n\t"
        "bra WL%=;\n\t"
        "WD%=:\n\t}"
        :: "r"(a), "r"(par) : "memory");
}
static __device__ __forceinline__ void mma8(float* d, const uint32_t* a,
                                            uint32_t b0, uint32_t b1) {
    asm volatile(
        "mma.sync.aligned.m16n8k8.row.col.f32.tf32.tf32.f32 "
        "{%0,%1,%2,%3}, {%4,%5,%6,%7}, {%8,%9}, {%0,%1,%2,%3};"
        : "+f"(d[0]), "+f"(d[1]), "+f"(d[2]), "+f"(d[3])
        : "r"(a[0]), "r"(a[1]), "r"(a[2]), "r"(a[3]), "r"(b0), "r"(b1));
}
static __device__ __forceinline__ void split_tf32(float v, float& hi, float& lo) {
    uint32_t u;
    asm("cvt.rna.tf32.f32 %0, %1;" : "=r"(u) : "f"(v));
    hi = __uint_as_float(u);
    lo = v - hi;
}

// ---------------- kernel 1: normalize + split + blocked/swizzled store ----------------
__global__ void norm_split_kernel(const float* __restrict__ fx, const float* __restrict__ fy) {
    int wid  = (blockIdx.x * blockDim.x + threadIdx.x) >> 5;
    int lane = threadIdx.x & 31;
    const int totx = BB * NX;
    if (wid >= totx + BB * NY) return;

    const float* src;
    float *dhi, *dlo;
    int blk0, rit;
    if (wid < totx) {
        int b = wid / NX, r = wid % NX;
        src = fx + (size_t)wid * DD;
        dhi = g_xhi; dlo = g_xlo;
        blk0 = (b * 32 + (r >> 7)) * 8;
        rit = r & 127;
    } else {
        int r0 = wid - totx;
        int b = r0 / NY, r = r0 % NY;
        src = fy + (size_t)r0 * DD;
        dhi = g_yhi; dlo = g_ylo;
        blk0 = (b * 64 + (r >> 7)) * 8;
        rit = r & 127;
    }
    float4 a = ((const float4*)src)[lane];
    float4 b4 = ((const float4*)src)[lane + 32];
    float s = a.x*a.x + a.y*a.y + a.z*a.z + a.w*a.w
            + b4.x*b4.x + b4.y*b4.y + b4.z*b4.z + b4.w*b4.w;
#pragma unroll
    for (int off = 16; off > 0; off >>= 1) s += __shfl_xor_sync(0xffffffffu, s, off);
    float inv = 1.0f / fmaxf(sqrtf(s), 1e-12f);

    float4 hi0, lo0, hi1, lo1;
    split_tf32(a.x * inv, hi0.x, lo0.x);  split_tf32(a.y * inv, hi0.y, lo0.y);
    split_tf32(a.z * inv, hi0.z, lo0.z);  split_tf32(a.w * inv, hi0.w, lo0.w);
    split_tf32(b4.x * inv, hi1.x, lo1.x); split_tf32(b4.y * inv, hi1.y, lo1.y);
    split_tf32(b4.z * inv, hi1.z, lo1.z); split_tf32(b4.w * inv, hi1.w, lo1.w);

    int q = lane & 7;
    int unit = q ^ (rit & 7);
    size_t slot0 = ((size_t)(blk0 + (lane >> 3)) * 1024) + rit * 8 + unit;
    size_t slot1 = ((size_t)(blk0 + 4 + (lane >> 3)) * 1024) + rit * 8 + unit;
    ((float4*)dhi)[slot0] = hi0;  ((float4*)dhi)[slot1] = hi1;
    ((float4*)dlo)[slot0] = lo0;  ((float4*)dlo)[slot1] = lo1;
}

// ---------------- kernel 2: pipelined mma.sync 3xTF32 GEMM + fused top-k ----------------
extern __shared__ unsigned char smem_raw[];

// fragment loader: 16 A regs (4 m-tiles) + 8 B regs (4 n-tiles)
static __device__ __forceinline__ void load_frags(
    uint32_t A, uint32_t Bq, int ks,
    uint32_t abase, uint32_t arsw, const uint32_t* bbase, uint32_t brsw,
    uint32_t afr[4][4], uint32_t bfr[4][2])
{
    const uint32_t u0 = (uint32_t)((2 * ks) ^ arsw) << 4;
    const uint32_t u1 = (uint32_t)((2 * ks + 1) ^ arsw) << 4;
#pragma unroll
    for (int m = 0; m < 4; m++) {
        uint32_t ab = A + abase + (uint32_t)(m * 16 * 128);
        afr[m][0] = lds32(ab + u0);
        afr[m][1] = lds32(ab + 8 * 128 + u0);
        afr[m][2] = lds32(ab + u1);
        afr[m][3] = lds32(ab + 8 * 128 + u1);
    }
    const uint32_t v0 = (uint32_t)((2 * ks) ^ brsw) << 4;
    const uint32_t v1 = (uint32_t)((2 * ks + 1) ^ brsw) << 4;
#pragma unroll
    for (int n = 0; n < 4; n++) {
        bfr[n][0] = lds32(Bq + bbase[n] + v0);
        bfr[n][1] = lds32(Bq + bbase[n] + v1);
    }
}

__global__ void __launch_bounds__(NTHR, 1)
sim_mma_kernel(float* __restrict__ out, int out_size) {
    const int b    = blockIdx.y;
    const int xt   = blockIdx.x;
    const int tid  = threadIdx.x;
    const int wid  = tid >> 5, lane = tid & 31;
    const int warpM = wid & 1;           // 2 warps along M (64 rows each)
    const int warpN = wid >> 1;          // 4 warps along N (32 cols each)
    const int gid  = lane >> 2;
    const int tig  = lane & 3;

    uint32_t s0 = cvta_s(smem_raw);
    float* SIM = (float*)(smem_raw + SM_SIM);
    float* LV  = (float*)(smem_raw + SM_LV);
    int*   LI  = (int*)(smem_raw + SM_LI);
    const uint32_t full0 = s0 + SM_CTRL,      full1 = s0 + SM_CTRL + 8;
    const uint32_t free0 = s0 + SM_CTRL + 16, free1 = s0 + SM_CTRL + 24;

    for (int i = tid; i < TMR * KK; i += NTHR) { LV[i] = -1e38f; LI[i] = 0; }
    if (tid == 0) {
        mb_init(full0, 1); mb_init(full1, 1);
        mb_init(free0, 8); mb_init(free1, 8);
    }
    __syncthreads();

    const int xblk0 = (b * 32 + xt) * 8;
    const int yblk0 = b * 64 * 8;

    uint32_t abase = (uint32_t)((warpM * 64 + gid) * 128 + tig * 4);
    const uint32_t arsw = (uint32_t)(gid & 7);
    uint32_t bbase[4];
#pragma unroll
    for (int n = 0; n < 4; n++)
        bbase[n] = (uint32_t)((warpN * 32 + n * 8 + gid) * 128 + tig * 4);
    const uint32_t brsw = (uint32_t)(gid & 7);

    float acc[4][4][4];

    // prologue: fill chunk 0 -> stage 0
    if (tid == 0) {
        mb_expect(full0, 65536);
        bulk16k(s0 + OFF_XHI, g_xhi + (size_t)xblk0 * BLKF, full0);
        bulk16k(s0 + OFF_XLO, g_xlo + (size_t)xblk0 * BLKF, full0);
        bulk16k(s0 + OFF_YHI, g_yhi + (size_t)yblk0 * BLKF, full0);
        bulk16k(s0 + OFF_YLO, g_ylo + (size_t)yblk0 * BLKF, full0);
    }

    for (int cc = 0; cc < CHTOT; cc++) {
        const int buf = cc & 1;
        const int c = cc & 7, t = cc >> 3;

        mb_wait(buf ? full1 : full0, (uint32_t)((cc >> 1) & 1));

        // producer refill of the other stage
        if (cc + 1 < CHTOT && tid == 0) {
            int nb = (cc + 1) & 1;
            int fi = (cc + 1) >> 1;
            if (fi >= 1) mb_wait(nb ? free1 : free0, (uint32_t)((fi - 1) & 1));
            int tn = (cc + 1) >> 3, cn = (cc + 1) & 7;
            uint32_t sb = s0 + (uint32_t)(nb * STG_SZ);
            uint32_t mbn = nb ? full1 : full0;
            mb_expect(mbn, 65536);
            bulk16k(sb + OFF_XHI, g_xhi + (size_t)(xblk0 + cn) * BLKF, mbn);
            bulk16k(sb + OFF_XLO, g_xlo + (size_t)(xblk0 + cn) * BLKF, mbn);
            bulk16k(sb + OFF_YHI, g_yhi + (size_t)(yblk0 + tn * 8 + cn) * BLKF, mbn);
            bulk16k(sb + OFF_YLO, g_ylo + (size_t)(yblk0 + tn * 8 + cn) * BLKF, mbn);
        }

        if (c == 0) {
#pragma unroll
            for (int m = 0; m < 4; m++)
#pragma unroll
                for (int n = 0; n < 4; n++)
#pragma unroll
                    for (int j = 0; j < 4; j++) acc[m][n][j] = 0.0f;
        }

        const uint32_t sb = s0 + (uint32_t)(buf * STG_SZ);
        // pass bases: hh, hl, lh (identical arithmetic order to R9/R10)
        const uint32_t Ab[3]  = {sb + OFF_XHI, sb + OFF_XHI, sb + OFF_XLO};
        const uint32_t Bbs[3] = {sb + OFF_YHI, sb + OFF_YLO, sb + OFF_YHI};

        // flat 12-step loop, fragments double-buffered one step ahead
        uint32_t afr[2][4][4], bfr[2][4][2];
        load_frags(Ab[0], Bbs[0], 0, abase, arsw, bbase, brsw, afr[0], bfr[0]);
#pragma unroll
        for (int s = 0; s < 12; s++) {
            const int d = s & 1;
            if (s < 11) {
                const int sn = s + 1;
                load_frags(Ab[sn >> 2], Bbs[sn >> 2], sn & 3,
                           abase, arsw, bbase, brsw, afr[sn & 1], bfr[sn & 1]);
            }
#pragma unroll
            for (int m = 0; m < 4; m++)
#pragma unroll
                for (int n = 0; n < 4; n++)
                    mma8(acc[m][n], afr[d][m], bfr[d][n][0], bfr[d][n][1]);
        }

        // declare stage free (operands consumed) — one arrive per warp
        if (lane == 0) mb_arrive(buf ? free1 : free0);

        // tile complete: stage SIM halves (64 rows each) + top-k scan
        if (c == 7) {
            const int col0 = t * TNC;
#pragma unroll
            for (int h = 0; h < 2; h++) {
                if (warpM == h) {
#pragma unroll
                    for (int m = 0; m < 4; m++) {
                        int r0 = m * 16 + gid;
#pragma unroll
                        for (int n = 0; n < 4; n++) {
                            int col = warpN * 32 + n * 8 + 2 * tig;
                            SIM[r0 * SIMP + col]           = acc[m][n][0];
                            SIM[r0 * SIMP + col + 1]       = acc[m][n][1];
                            SIM[(r0 + 8) * SIMP + col]     = acc[m][n][2];
                            SIM[(r0 + 8) * SIMP + col + 1] = acc[m][n][3];
                        }
                    }
                }
                __syncthreads();
                if (tid < 64) {
                    int row = h * 64 + tid;
                    float* lv = LV + row * KK;
                    int*   li = LI + row * KK;
                    const float* srow = SIM + tid * SIMP;
                    float lv9 = lv[KK - 1];
#pragma unroll 4
                    for (int cL = 0; cL < TNC; cL++) {
                        float vv = srow[cL];
                        if (vv > lv9) {
                            int p = KK - 1;
                            while (p > 0 && lv[p - 1] < vv) {
                                lv[p] = lv[p - 1]; li[p] = li[p - 1]; --p;
                            }
                            lv[p] = vv; li[p] = col0 + cL;
                            lv9 = lv[KK - 1];
                        }
                    }
                }
                __syncthreads();
            }
        }
    }

    // ---- finalize: softmax + sort-by-col + write ----
    if (tid < TMR) {
        float v[KK]; int ix[KK];
#pragma unroll
        for (int k = 0; k < KK; k++) { v[k] = LV[tid * KK + k]; ix[k] = LI[tid * KK + k]; }
        float m = v[0];
        float e[KK]; float ssum = 0.0f;
#pragma unroll
        for (int k = 0; k < KK; k++) { e[k] = expf((v[k] - m) * INV_TAU); ssum += e[k]; }
        float inv = 1.0f / ssum;
#pragma unroll
        for (int a = 1; a < KK; a++) {
            int ki = ix[a]; float ke = e[a]; int p = a;
            while (p > 0 && ix[p - 1] > ki) { ix[p] = ix[p - 1]; e[p] = e[p - 1]; --p; }
            ix[p] = ki; e[p] = ke;
        }
        int gRow = xt * TMR + tid;
        size_t basev = ((size_t)b * NX + gRow) * KK;
        bool write_idx = (out_size >= 4 * NVAL);
#pragma unroll
        for (int k = 0; k < KK; k++) {
            out[basev + k] = e[k] * inv;
            if (write_idx) {
                out[(size_t)NVAL     + basev + k] = (float)b;
                out[(size_t)2 * NVAL + basev + k] = (float)gRow;
                out[(size_t)3 * NVAL + basev + k] = (float)ix[k];
            }
        }
    }
}

// ---------------- launch ----------------
extern "C" void kernel_launch(void* const* d_in, const int* in_sizes, int n_in,
                              void* d_out, int out_size) {
    const float* fx = (const float*)d_in[0];
    const float* fy = (const float*)d_in[1];
    float* out = (float*)d_out;

    int nrows = BB * NX + BB * NY;
    norm_split_kernel<<<(nrows + 7) / 8, 256>>>(fx, fy);

    cudaFuncSetAttribute(sim_mma_kernel,
                         cudaFuncAttributeMaxDynamicSharedMemorySize, SM_TOT);
    dim3 g2(NX / TMR, BB);                     // 128 CTAs
    sim_mma_kernel<<<g2, NTHR, SM_TOT>>>(out, out_size);
}

// round 12
// speedup vs baseline: 1.7858x; 1.2874x over previous
#include <cuda_runtime.h>
#include <cuda_fp16.h>
#include <cstdint>
#include <math.h>

// ---------------- problem constants ----------------
#define BB   4
#define NX   4096
#define NY   8192
#define DD   256
#define TMR  128                 // x rows per CTA
#define TNC  128                 // y cols per tile
#define KCH  64                  // k per chunk (fp16: 128B row)
#define NTIL (NY / TNC)          // 64 y tiles
#define NCHK (DD / KCH)          // 4 chunks per tile
#define CHTOT (NTIL * NCHK)      // 256 chunk iterations
#define KK   10
#define NVAL (BB * NX * KK)      // 163840
#define INV_TAU 20.0f
#define NTHR 256
#define BLKB 16384               // bytes per block (128 rows x 64 k x 2B)

// blocked + swizzled fp16-split scratch
// block idx: X: ((b*32+xt)*4 + c), Y: ((b*64+t)*4 + c)
// within block: row(0..127) x 8 units(16B); unit' = unit ^ (row&7)
__device__ __align__(128) __half g_xh[(size_t)BB * NX * DD];
__device__ __align__(128) __half g_xl[(size_t)BB * NX * DD];
__device__ __align__(128) __half g_yh[(size_t)BB * NY * DD];
__device__ __align__(128) __half g_yl[(size_t)BB * NY * DD];

// ---------------- smem layout (bytes) ----------------
#define STG_SZ  65536
#define OFF_XH  0
#define OFF_XL  16384
#define OFF_YH  32768
#define OFF_YL  49152
#define SM_SIM  131072               // 64 x 133 floats = 34048
#define SM_LV   165120
#define SM_LI   170240
#define SM_CTRL 175360               // full0,full1,free0,free1
#define SM_TOT  175424
#define SIMP    133

// ---------------- helpers ----------------
static __device__ __forceinline__ uint32_t cvta_s(const void* p) {
    return (uint32_t)__cvta_generic_to_shared(p);
}
static __device__ __forceinline__ uint32_t lds32(uint32_t a) {
    uint32_t v;
    asm volatile("ld.shared.b32 %0, [%1];" : "=r"(v) : "r"(a));
    return v;
}
static __device__ __forceinline__ void bulk16k(uint32_t dst, const void* src, uint32_t mbar) {
    asm volatile(
        "cp.async.bulk.shared::cta.global.mbarrier::complete_tx::bytes [%0], [%1], %2, [%3];"
        :: "r"(dst), "l"(src), "r"(16384u), "r"(mbar) : "memory");
}
static __device__ __forceinline__ void mb_init(uint32_t a, uint32_t c) {
    asm volatile("mbarrier.init.shared.b64 [%0], %1;" :: "r"(a), "r"(c) : "memory");
}
static __device__ __forceinline__ void mb_expect(uint32_t a, uint32_t bytes) {
    asm volatile("mbarrier.arrive.expect_tx.shared.b64 _, [%0], %1;" :: "r"(a), "r"(bytes) : "memory");
}
static __device__ __forceinline__ void mb_arrive(uint32_t a) {
    asm volatile("mbarrier.arrive.shared.b64 _, [%0];" :: "r"(a) : "memory");
}
static __device__ __forceinline__ void mb_wait(uint32_t a, uint32_t par) {
    asm volatile(
        "{\n\t.reg .pred P;\n\t"
        "WL%=:\n\t"
        "mbarrier.try_wait.parity.acquire.cta.shared::cta.b64 P, [%0], %1, 0x989680;\n\t"
        "@P bra WD%=;\n\t"
        "bra WL%=;\n\t"
        "WD%=:\n\t}"
        :: "r"(a), "r"(par) : "memory");
}
static __device__ __forceinline__ void mma16f(float* d, const uint32_t* a,
                                              uint32_t b0, uint32_t b1) {
    asm volatile(
        "mma.sync.aligned.m16n8k16.row.col.f32.f16.f16.f32 "
        "{%0,%1,%2,%3}, {%4,%5,%6,%7}, {%8,%9}, {%0,%1,%2,%3};"
        : "+f"(d[0]), "+f"(d[1]), "+f"(d[2]), "+f"(d[3])
        : "r"(a[0]), "r"(a[1]), "r"(a[2]), "r"(a[3]), "r"(b0), "r"(b1));
}

// ---------------- kernel 1: normalize + fp16-split + blocked/swizzled store ----------------
__global__ void norm_split_kernel(const float* __restrict__ fx, const float* __restrict__ fy) {
    int wid  = (blockIdx.x * blockDim.x + threadIdx.x) >> 5;
    int lane = threadIdx.x & 31;
    const int totx = BB * NX;
    if (wid >= totx + BB * NY) return;

    const float* src;
    __half *dh, *dl;
    int blk0, rit;
    if (wid < totx) {
        int b = wid / NX, r = wid % NX;
        src = fx + (size_t)wid * DD;
        dh = g_xh; dl = g_xl;
        blk0 = (b * 32 + (r >> 7)) * 4;
        rit = r & 127;
    } else {
        int r0 = wid - totx;
        int b = r0 / NY, r = r0 % NY;
        src = fy + (size_t)r0 * DD;
        dh = g_yh; dl = g_yl;
        blk0 = (b * 64 + (r >> 7)) * 4;
        rit = r & 127;
    }
    float4 a = ((const float4*)src)[lane];
    float4 b4 = ((const float4*)src)[lane + 32];
    float s = a.x*a.x + a.y*a.y + a.z*a.z + a.w*a.w
            + b4.x*b4.x + b4.y*b4.y + b4.z*b4.z + b4.w*b4.w;
#pragma unroll
    for (int off = 16; off > 0; off >>= 1) s += __shfl_xor_sync(0xffffffffu, s, off);
    float inv = 1.0f / fmaxf(sqrtf(s), 1e-12f);

    float va[4] = {a.x*inv, a.y*inv, a.z*inv, a.w*inv};
    float vb[4] = {b4.x*inv, b4.y*inv, b4.z*inv, b4.w*inv};

    __half ha[4], la[4], hb[4], lb[4];
#pragma unroll
    for (int i = 0; i < 4; i++) {
        ha[i] = __float2half_rn(va[i]);
        la[i] = __float2half_rn(va[i] - __half2float(ha[i]));
        hb[i] = __float2half_rn(vb[i]);
        lb[i] = __float2half_rn(vb[i] - __half2float(hb[i]));
    }

    // group A: k = 4*lane .. 4*lane+3 (chunk lane>>4); group B: k+128 (chunk 2+(lane>>4))
    int kw  = (4 * lane) & 63;
    int u   = kw >> 3;
    int hoff = kw & 7;                       // 0 or 4
    size_t slotA = (size_t)(blk0 + (lane >> 4)) * 8192
                 + rit * 64 + (size_t)((u ^ (rit & 7)) * 8 + hoff);
    size_t slotB = (size_t)(blk0 + 2 + (lane >> 4)) * 8192
                 + rit * 64 + (size_t)((u ^ (rit & 7)) * 8 + hoff);

    uint2 wha, wla, whb, wlb;
    wha.x = __half2uint_rn(0); // placate compiler init (overwritten)
    wha = make_uint2(__halves2half2(ha[0], ha[1]).x ? 0u : 0u, 0u);
    // pack via memcpy-safe reinterpretation
    {
        __half2 p0 = __halves2half2(ha[0], ha[1]);
        __half2 p1 = __halves2half2(ha[2], ha[3]);
        wha.x = *(uint32_t*)&p0; wha.y = *(uint32_t*)&p1;
        p0 = __halves2half2(la[0], la[1]); p1 = __halves2half2(la[2], la[3]);
        wla.x = *(uint32_t*)&p0; wla.y = *(uint32_t*)&p1;
        p0 = __halves2half2(hb[0], hb[1]); p1 = __halves2half2(hb[2], hb[3]);
        whb.x = *(uint32_t*)&p0; whb.y = *(uint32_t*)&p1;
        p0 = __halves2half2(lb[0], lb[1]); p1 = __halves2half2(lb[2], lb[3]);
        wlb.x = *(uint32_t*)&p0; wlb.y = *(uint32_t*)&p1;
    }
    *(uint2*)((char*)dh + slotA * 2) = wha;
    *(uint2*)((char*)dl + slotA * 2) = wla;
    *(uint2*)((char*)dh + slotB * 2) = whb;
    *(uint2*)((char*)dl + slotB * 2) = wlb;
}

// ---------------- kernel 2: pipelined fp16 3-pass GEMM + fused top-k ----------------
extern __shared__ unsigned char smem_raw[];

static __device__ __forceinline__ void load_frags(
    uint32_t A, uint32_t Bq, int ks,
    uint32_t abase, uint32_t key, const uint32_t* bbase,
    uint32_t afr[4][4], uint32_t bfr[4][2])
{
    const uint32_t u0 = (uint32_t)((2 * ks) ^ key) << 4;
    const uint32_t u1 = (uint32_t)((2 * ks + 1) ^ key) << 4;
#pragma unroll
    for (int m = 0; m < 4; m++) {
        uint32_t ab = A + abase + (uint32_t)(m * 16 * 128);
        afr[m][0] = lds32(ab + u0);
        afr[m][1] = lds32(ab + 8 * 128 + u0);
        afr[m][2] = lds32(ab + u1);
        afr[m][3] = lds32(ab + 8 * 128 + u1);
    }
#pragma unroll
    for (int n = 0; n < 4; n++) {
        bfr[n][0] = lds32(Bq + bbase[n] + u0);
        bfr[n][1] = lds32(Bq + bbase[n] + u1);
    }
}

__global__ void __launch_bounds__(NTHR, 1)
sim_mma_kernel(float* __restrict__ out, int out_size) {
    const int b    = blockIdx.y;
    const int xt   = blockIdx.x;
    const int tid  = threadIdx.x;
    const int wid  = tid >> 5, lane = tid & 31;
    const int warpM = wid & 1;           // 2 warps along M (64 rows each)
    const int warpN = wid >> 1;          // 4 warps along N (32 cols each)
    const int gid  = lane >> 2;
    const int tig  = lane & 3;

    uint32_t s0 = cvta_s(smem_raw);
    float* SIM = (float*)(smem_raw + SM_SIM);
    float* LV  = (float*)(smem_raw + SM_LV);
    int*   LI  = (int*)(smem_raw + SM_LI);
    const uint32_t full0 = s0 + SM_CTRL,      full1 = s0 + SM_CTRL + 8;
    const uint32_t free0 = s0 + SM_CTRL + 16, free1 = s0 + SM_CTRL + 24;

    for (int i = tid; i < TMR * KK; i += NTHR) { LV[i] = -1e38f; LI[i] = 0; }
    if (tid == 0) {
        mb_init(full0, 1); mb_init(full1, 1);
        mb_init(free0, 8); mb_init(free1, 8);
    }
    __syncthreads();

    const int xblk0 = (b * 32 + xt) * 4;
    const int yblk0 = b * 64 * 4;

    uint32_t abase = (uint32_t)((warpM * 64 + gid) * 128 + tig * 4);
    const uint32_t key = (uint32_t)(gid & 7);
    uint32_t bbase[4];
#pragma unroll
    for (int n = 0; n < 4; n++)
        bbase[n] = (uint32_t)((warpN * 32 + n * 8 + gid) * 128 + tig * 4);

    float acc[4][4][4];

    // prologue: fill chunk 0 -> stage 0
    if (tid == 0) {
        mb_expect(full0, 65536);
        bulk16k(s0 + OFF_XH, (const char*)g_xh + (size_t)xblk0 * BLKB, full0);
        bulk16k(s0 + OFF_XL, (const char*)g_xl + (size_t)xblk0 * BLKB, full0);
        bulk16k(s0 + OFF_YH, (const char*)g_yh + (size_t)yblk0 * BLKB, full0);
        bulk16k(s0 + OFF_YL, (const char*)g_yl + (size_t)yblk0 * BLKB, full0);
    }

    for (int cc = 0; cc < CHTOT; cc++) {
        const int buf = cc & 1;
        const int c = cc & 3, t = cc >> 2;

        mb_wait(buf ? full1 : full0, (uint32_t)((cc >> 1) & 1));

        // producer refill of the other stage
        if (cc + 1 < CHTOT && tid == 0) {
            int nb = (cc + 1) & 1;
            int fi = (cc + 1) >> 1;
            if (fi >= 1) mb_wait(nb ? free1 : free0, (uint32_t)((fi - 1) & 1));
            int tn = (cc + 1) >> 2, cn = (cc + 1) & 3;
            uint32_t sb = s0 + (uint32_t)(nb * STG_SZ);
            uint32_t mbn = nb ? full1 : full0;
            mb_expect(mbn, 65536);
            bulk16k(sb + OFF_XH, (const char*)g_xh + (size_t)(xblk0 + cn) * BLKB, mbn);
            bulk16k(sb + OFF_XL, (const char*)g_xl + (size_t)(xblk0 + cn) * BLKB, mbn);
            bulk16k(sb + OFF_YH, (const char*)g_yh + (size_t)(yblk0 + tn * 4 + cn) * BLKB, mbn);
            bulk16k(sb + OFF_YL, (const char*)g_yl + (size_t)(yblk0 + tn * 4 + cn) * BLKB, mbn);
        }

        if (c == 0) {
#pragma unroll
            for (int m = 0; m < 4; m++)
#pragma unroll
                for (int n = 0; n < 4; n++)
#pragma unroll
                    for (int j = 0; j < 4; j++) acc[m][n][j] = 0.0f;
        }

        const uint32_t sb = s0 + (uint32_t)(buf * STG_SZ);
        // passes: hh, hl, lh
        const uint32_t Ab[3]  = {sb + OFF_XH, sb + OFF_XH, sb + OFF_XL};
        const uint32_t Bbs[3] = {sb + OFF_YH, sb + OFF_YL, sb + OFF_YH};

        // flat 12-step loop (3 pass x 4 ks of k16), fragments double-buffered
        uint32_t afr[2][4][4], bfr[2][4][2];
        load_frags(Ab[0], Bbs[0], 0, abase, key, bbase, afr[0], bfr[0]);
#pragma unroll
        for (int s = 0; s < 12; s++) {
            const int d = s & 1;
            if (s < 11) {
                const int sn = s + 1;
                load_frags(Ab[sn >> 2], Bbs[sn >> 2], sn & 3,
                           abase, key, bbase, afr[sn & 1], bfr[sn & 1]);
            }
#pragma unroll
            for (int m = 0; m < 4; m++)
#pragma unroll
                for (int n = 0; n < 4; n++)
                    mma16f(acc[m][n], afr[d][m], bfr[d][n][0], bfr[d][n][1]);
        }

        if (lane == 0) mb_arrive(buf ? free1 : free0);

        // tile complete: stage SIM halves + top-k scan
        if (c == 3) {
            const int col0 = t * TNC;
#pragma unroll
            for (int h = 0; h < 2; h++) {
                if (warpM == h) {
#pragma unroll
                    for (int m = 0; m < 4; m++) {
                        int r0 = m * 16 + gid;
#pragma unroll
                        for (int n = 0; n < 4; n++) {
                            int col = warpN * 32 + n * 8 + 2 * tig;
                            SIM[r0 * SIMP + col]           = acc[m][n][0];
                            SIM[r0 * SIMP + col + 1]       = acc[m][n][1];
                            SIM[(r0 + 8) * SIMP + col]     = acc[m][n][2];
                            SIM[(r0 + 8) * SIMP + col + 1] = acc[m][n][3];
                        }
                    }
                }
                __syncthreads();
                if (tid < 64) {
                    int row = h * 64 + tid;
                    float* lv = LV + row * KK;
                    int*   li = LI + row * KK;
                    const float* srow = SIM + tid * SIMP;
                    float lv9 = lv[KK - 1];
#pragma unroll 4
                    for (int cL = 0; cL < TNC; cL++) {
                        float vv = srow[cL];
                        if (vv > lv9) {
                            int p = KK - 1;
                            while (p > 0 && lv[p - 1] < vv) {
                                lv[p] = lv[p - 1]; li[p] = li[p - 1]; --p;
                            }
                            lv[p] = vv; li[p] = col0 + cL;
                            lv9 = lv[KK - 1];
                        }
                    }
                }
                __syncthreads();
            }
        }
    }

    // ---- finalize: softmax + sort-by-col + write ----
    if (tid < TMR) {
        float v[KK]; int ix[KK];
#pragma unroll
        for (int k = 0; k < KK; k++) { v[k] = LV[tid * KK + k]; ix[k] = LI[tid * KK + k]; }
        float m = v[0];
        float e[KK]; float ssum = 0.0f;
#pragma unroll
        for (int k = 0; k < KK; k++) { e[k] = expf((v[k] - m) * INV_TAU); ssum += e[k]; }
        float inv = 1.0f / ssum;
#pragma unroll
        for (int a = 1; a < KK; a++) {
            int ki = ix[a]; float ke = e[a]; int p = a;
            while (p > 0 && ix[p - 1] > ki) { ix[p] = ix[p - 1]; e[p] = e[p - 1]; --p; }
            ix[p] = ki; e[p] = ke;
        }
        int gRow = xt * TMR + tid;
        size_t basev = ((size_t)b * NX + gRow) * KK;
        bool write_idx = (out_size >= 4 * NVAL);
#pragma unroll
        for (int k = 0; k < KK; k++) {
            out[basev + k] = e[k] * inv;
            if (write_idx) {
                out[(size_t)NVAL     + basev + k] = (float)b;
                out[(size_t)2 * NVAL + basev + k] = (float)gRow;
                out[(size_t)3 * NVAL + basev + k] = (float)ix[k];
            }
        }
    }
}

// ---------------- launch ----------------
extern "C" void kernel_launch(void* const* d_in, const int* in_sizes, int n_in,
                              void* d_out, int out_size) {
    const float* fx = (const float*)d_in[0];
    const float* fy = (const float*)d_in[1];
    float* out = (float*)d_out;

    int nrows = BB * NX + BB * NY;
    norm_split_kernel<<<(nrows + 7) / 8, 256>>>(fx, fy);

    cudaFuncSetAttribute(sim_mma_kernel,
                         cudaFuncAttributeMaxDynamicSharedMemorySize, SM_TOT);
    dim3 g2(NX / TMR, BB);                     // 128 CTAs
    sim_mma_kernel<<<g2, NTHR, SM_TOT>>>(out, out_size);
}